// round 2
// baseline (speedup 1.0000x reference)
#include <cuda_runtime.h>
#include <cuda_bf16.h>

// RoIAlign1D: feat [B,T,D] f32, spans [B,K,2] i32, lengths [B] i32 -> out [B,K,P,D] f32
// P = 16, D = 512 (128 float4).
//
// R2 layout: one block per RoI (b,k). 128 threads; thread tid owns float4 lane
// tid for all 16 pooled samples. Span math once per block (amortized over 48
// memory ops/thread). Inner loop unrolled x4 -> 8 independent LDG.128 in
// flight per thread. Grid = B*K = 1024 blocks -> single wave on 148 SMs.

#define P_SAMPLES 16

__global__ void __launch_bounds__(128) roialign1d_kernel(
    const float4* __restrict__ feat,   // [B, T, 128]
    const int*    __restrict__ spans,  // [B, K, 2]
    const int*    __restrict__ lengths,// [B]
    float4*       __restrict__ out,    // [B, K, P, 128]
    int K, int T, int D4)
{
    const int bk  = blockIdx.x;                  // b*K + k
    const int b   = bk / K;
    const int tid = threadIdx.x;                 // d4 lane, 0..127

    // ---- span math, once per block (uniform) ----
    const int Lm1 = __ldg(&lengths[b]) - 1;
    int a0 = __ldg(&spans[bk * 2 + 0]);
    int a1 = __ldg(&spans[bk * 2 + 1]);
    a0 = min(max(a0, 0), Lm1);
    a1 = min(max(a1, 0), Lm1);
    const int s     = min(a0, a1);
    const int segm1 = max(a0, a1) - s;           // seglen - 1
    const float segf = (float)segm1;

    const long long fbase = (long long)(b * T + s) * D4 + tid;
    const long long obase = (long long)bk * (P_SAMPLES * (long long)D4) + tid;

    #pragma unroll
    for (int p = 0; p < P_SAMPLES; p += 4) {
        float4 f0[4], f1[4];
        float  w[4];
        // issue all 8 loads before consuming any -> MLP 8
        #pragma unroll
        for (int u = 0; u < 4; u++) {
            const int pp = p + u;
            const float t   = (float)pp / (float)(P_SAMPLES - 1); // const-folded p/15
            const float idx = t * segf;
            int i0 = (int)floorf(idx);
            i0 = min(i0, segm1);
            const int i1 = min(i0 + 1, segm1);
            w[u] = idx - (float)i0;
            f0[u] = feat[fbase + (long long)i0 * D4];
            f1[u] = feat[fbase + (long long)i1 * D4];
        }
        #pragma unroll
        for (int u = 0; u < 4; u++) {
            const float wm = 1.0f - w[u];
            float4 r;
            r.x = wm * f0[u].x + w[u] * f1[u].x;
            r.y = wm * f0[u].y + w[u] * f1[u].y;
            r.z = wm * f0[u].z + w[u] * f1[u].z;
            r.w = wm * f0[u].w + w[u] * f1[u].w;
            out[obase + (long long)(p + u) * D4] = r;
        }
    }
}

extern "C" void kernel_launch(void* const* d_in, const int* in_sizes, int n_in,
                              void* d_out, int out_size)
{
    const float* feat    = (const float*)d_in[0];
    const int*   spans   = (const int*)d_in[1];
    const int*   lengths = (const int*)d_in[2];
    float*       out     = (float*)d_out;

    const int B  = in_sizes[2];                      // 16
    const int K  = in_sizes[1] / (2 * B);            // 64
    const int TD = in_sizes[0] / B;                  // T*D
    const int D  = out_size / (B * K * P_SAMPLES);   // 512
    const int T  = TD / D;                           // 4096
    const int D4 = D / 4;                            // 128

    const int nblocks = B * K;                       // 1024
    roialign1d_kernel<<<nblocks, D4>>>(
        (const float4*)feat, spans, lengths, (float4*)out, K, T, D4);
}

// round 3
// speedup vs baseline: 1.3922x; 1.3922x over previous
#include <cuda_runtime.h>
#include <cuda_bf16.h>

// RoIAlign1D: feat [B,T,D] f32, spans [B,K,2] i32, lengths [B] i32 -> out [B,K,P,D] f32
// P = 16, D = 512 (128 float4).
//
// R3 layout: one block per (RoI, 4-sample group). Grid = B*K*4 = 4096 blocks,
// 128 threads. Thread tid owns float4 lane tid for its 4 samples: 8 independent
// LDG.128 in flight (MLP=8), span math amortized over 12 memory ops, and
// 4096 blocks keeps occupancy near the register cap (~60 warps/SM).

#define P_SAMPLES 16
#define PG 4   // samples per block

__global__ void __launch_bounds__(128) roialign1d_kernel(
    const float4* __restrict__ feat,   // [B, T, 128]
    const int*    __restrict__ spans,  // [B, K, 2]
    const int*    __restrict__ lengths,// [B]
    float4*       __restrict__ out,    // [B, K, P, 128]
    int K, int T, int D4)
{
    const int blk = blockIdx.x;                  // bk*4 + pg
    const int pg  = blk & 3;
    const int bk  = blk >> 2;                    // b*K + k
    const int b   = bk / K;
    const int tid = threadIdx.x;                 // d4 lane, 0..127

    // ---- span math, once per block (uniform) ----
    const int Lm1 = __ldg(&lengths[b]) - 1;
    int a0 = __ldg(&spans[bk * 2 + 0]);
    int a1 = __ldg(&spans[bk * 2 + 1]);
    a0 = min(max(a0, 0), Lm1);
    a1 = min(max(a1, 0), Lm1);
    const int s     = min(a0, a1);
    const int segm1 = max(a0, a1) - s;           // seglen - 1
    const float segf = (float)segm1;

    const long long fbase = (long long)(b * T + s) * D4 + tid;
    const long long obase = (long long)bk * (P_SAMPLES * (long long)D4)
                          + (long long)(pg * PG) * D4 + tid;

    float4 f0[PG], f1[PG];
    float  w[PG];
    #pragma unroll
    for (int u = 0; u < PG; u++) {
        const int pp = pg * PG + u;
        const float t   = (float)pp / (float)(P_SAMPLES - 1);
        const float idx = t * segf;
        int i0 = (int)floorf(idx);
        i0 = min(i0, segm1);
        const int i1 = min(i0 + 1, segm1);
        w[u] = idx - (float)i0;
        f0[u] = feat[fbase + (long long)i0 * D4];
        f1[u] = feat[fbase + (long long)i1 * D4];
    }
    #pragma unroll
    for (int u = 0; u < PG; u++) {
        const float wm = 1.0f - w[u];
        float4 r;
        r.x = wm * f0[u].x + w[u] * f1[u].x;
        r.y = wm * f0[u].y + w[u] * f1[u].y;
        r.z = wm * f0[u].z + w[u] * f1[u].z;
        r.w = wm * f0[u].w + w[u] * f1[u].w;
        out[obase + (long long)u * D4] = r;
    }
}

extern "C" void kernel_launch(void* const* d_in, const int* in_sizes, int n_in,
                              void* d_out, int out_size)
{
    const float* feat    = (const float*)d_in[0];
    const int*   spans   = (const int*)d_in[1];
    const int*   lengths = (const int*)d_in[2];
    float*       out     = (float*)d_out;

    const int B  = in_sizes[2];                      // 16
    const int K  = in_sizes[1] / (2 * B);            // 64
    const int TD = in_sizes[0] / B;                  // T*D
    const int D  = out_size / (B * K * P_SAMPLES);   // 512
    const int T  = TD / D;                           // 4096
    const int D4 = D / 4;                            // 128

    const int nblocks = B * K * (P_SAMPLES / PG);    // 4096
    roialign1d_kernel<<<nblocks, D4>>>(
        (const float4*)feat, spans, lengths, (float4*)out, K, T, D4);
}

// round 4
// speedup vs baseline: 1.5099x; 1.0845x over previous
#include <cuda_runtime.h>
#include <cuda_bf16.h>

// RoIAlign1D: feat [B,T,D] f32, spans [B,K,2] i32, lengths [B] i32 -> out [B,K,P,D] f32
// P = 16, D = 512 (128 float4).
//
// R4: same (RoI, 4-sample group) blocking as R3 (grid=4096, 128 thr, MLP=8)
// but with 32-bit offsets + __launch_bounds__(128,12) to cut regs 47 -> <=42
// (48 warps/SM) and __stcs streaming stores to keep L2 for feat reads.

#define P_SAMPLES 16
#define PG 4   // samples per block

__global__ void __launch_bounds__(128, 12) roialign1d_kernel(
    const float4* __restrict__ feat,   // [B, T, 128]
    const int*    __restrict__ spans,  // [B, K, 2]
    const int*    __restrict__ lengths,// [B]
    float4*       __restrict__ out,    // [B, K, P, 128]
    int K, int T, int D4)
{
    const int blk = blockIdx.x;                  // bk*4 + pg
    const int pg  = blk & 3;
    const int bk  = blk >> 2;                    // b*K + k
    const int b   = bk / K;
    const int tid = threadIdx.x;                 // d4 lane, 0..127

    // ---- span math, once per block (uniform) ----
    const int Lm1 = __ldg(&lengths[b]) - 1;
    int a0 = __ldg(&spans[bk * 2 + 0]);
    int a1 = __ldg(&spans[bk * 2 + 1]);
    a0 = min(max(a0, 0), Lm1);
    a1 = min(max(a1, 0), Lm1);
    const int s     = min(a0, a1);
    const int segm1 = max(a0, a1) - s;           // seglen - 1
    const float segf = (float)segm1;

    // 32-bit offsets (max feat float4 index 8.4M, out 16.8M -> fits int)
    const int fbase = (b * T + s) * D4 + tid;
    const int obase = (bk * P_SAMPLES + pg * PG) * D4 + tid;

    float4 f0[PG], f1[PG];
    float  w[PG];
    #pragma unroll
    for (int u = 0; u < PG; u++) {
        const int pp = pg * PG + u;
        const float t   = (float)pp / (float)(P_SAMPLES - 1);
        const float idx = t * segf;
        int i0 = (int)floorf(idx);
        i0 = min(i0, segm1);
        const int i1 = min(i0 + 1, segm1);
        w[u] = idx - (float)i0;
        f0[u] = feat[fbase + i0 * D4];
        f1[u] = feat[fbase + i1 * D4];
    }
    #pragma unroll
    for (int u = 0; u < PG; u++) {
        const float wm = 1.0f - w[u];
        float4 r;
        r.x = wm * f0[u].x + w[u] * f1[u].x;
        r.y = wm * f0[u].y + w[u] * f1[u].y;
        r.z = wm * f0[u].z + w[u] * f1[u].z;
        r.w = wm * f0[u].w + w[u] * f1[u].w;
        __stcs(&out[obase + u * D4], r);         // streaming store: keep L2 for feat
    }
}

extern "C" void kernel_launch(void* const* d_in, const int* in_sizes, int n_in,
                              void* d_out, int out_size)
{
    const float* feat    = (const float*)d_in[0];
    const int*   spans   = (const int*)d_in[1];
    const int*   lengths = (const int*)d_in[2];
    float*       out     = (float*)d_out;

    const int B  = in_sizes[2];                      // 16
    const int K  = in_sizes[1] / (2 * B);            // 64
    const int TD = in_sizes[0] / B;                  // T*D
    const int D  = out_size / (B * K * P_SAMPLES);   // 512
    const int T  = TD / D;                           // 4096
    const int D4 = D / 4;                            // 128

    const int nblocks = B * K * (P_SAMPLES / PG);    // 4096
    roialign1d_kernel<<<nblocks, D4>>>(
        (const float4*)feat, spans, lengths, (float4*)out, K, T, D4);
}